// round 16
// baseline (speedup 1.0000x reference)
#include <cuda_runtime.h>

// FastLearnableEMA — register-resident float4 kernel, no smem staging.
//   a    = clip(sigmoid(logit_alpha), 1e-4, 1-1e-4)             [C]
//   u[t] = x[t]*w[t],  w[0]=1, w[t>0]=(1-a)*a^t
//   y[t] = cumsum_t(u) * min(a^-t, 1e8)     (== cumsum / max(a^t, 1e-8))
//
// Thread owns 4 consecutive channels (float4) x 4 t per chunk: LDG.128 in,
// STG.128 out — 4x fewer memory instructions than the staged versions, and
// the in-chunk prefix is computed in place so the fma chain runs once.
// Block = 128 thr = 32 chunks x 4 channel-groups; tile = 128 t; 16 tiles.
// grid = 1024 CTAs @ 8/SM (single wave). One barrier per tile via parity
// double-buffered sm_part/sm_base. 256 MB compulsory HBM traffic.

#define T_LEN   2048
#define C_LEN   512
#define CT      16                 // channels per block (4 float4 groups)
#define NCHUNK  32                 // chunks per tile
#define LT      4                  // t per chunk
#define TILE_T  (NCHUNK * LT)      // 128
#define NTILES  (T_LEN / TILE_T)   // 16
#define CLAMP_LO 1e-4f
#define CLAMP_HI (1.0f - 1e-4f)
#define INV_EPS  1e8f              // 1/eps

__global__ void __launch_bounds__(128, 8) ema_fused(
    const float* __restrict__ x,
    const float* __restrict__ logit_alpha,
    float* __restrict__ y)
{
    const int tid = threadIdx.x;
    const int k   = tid >> 2;                     // chunk id 0..31
    const int cg  = tid & 3;                      // channel group 0..3
    const int b   = blockIdx.x >> 5;              // C/CT = 32 ctiles per b
    const int ct  = blockIdx.x & 31;
    const int c0  = ct * CT + cg * 4;             // first of 4 channels

    __shared__ float sm_part[2][NCHUNK][CT];
    __shared__ float sm_base[2][CT];

    // per-channel constants (4 channels per thread)
    float a[4], oma[4], inv_a[4], ap[4], iap[4], aT[4], iaT[4];
    {
        const float4 la4 = *(const float4*)(logit_alpha + c0);
        const float lav[4] = {la4.x, la4.y, la4.z, la4.w};
        const float t0k = (float)(k * LT);
        #pragma unroll
        for (int j = 0; j < 4; j++) {
            float av = 1.0f / (1.0f + expf(-lav[j]));
            av = fminf(fmaxf(av, CLAMP_LO), CLAMP_HI);
            a[j] = av; oma[j] = 1.0f - av; inv_a[j] = 1.0f / av;
            float l2 = log2f(av);
            ap[j]  = (k == 0) ? 1.0f : exp2f( t0k * l2);  // a^{k*LT}
            iap[j] = (k == 0) ? 1.0f : exp2f(-t0k * l2);  // a^{-k*LT}
            float at = av, iat = inv_a[j];
            #pragma unroll
            for (int s = 0; s < 7; s++) { at *= at; iat *= iat; }
            aT[j] = at;   // a^128   (underflow->0 ok, matches reference)
            iaT[j] = iat; // a^-128  (overflow->inf ok, clamped at use)
        }
    }

    if (tid < CT) sm_base[0][tid] = 0.0f;         // ordered by first barrier

    const size_t off0 = (size_t)b * T_LEN * C_LEN + (size_t)(k * LT) * C_LEN + c0;
    const float* xp0 = x + off0;
    float*       yp0 = y + off0;

    #pragma unroll 1
    for (int tile = 0; tile < NTILES; tile++) {
        const int p = tile & 1;
        const float* xp = xp0 + (size_t)tile * TILE_T * C_LEN;
        float*       yp = yp0 + (size_t)tile * TILE_T * C_LEN;

        // ---- load 4 t-rows x 4 channels, straight to registers
        float4 v4[LT];
        #pragma unroll
        for (int i = 0; i < LT; i++)
            v4[i] = __ldcs((const float4*)(xp + (size_t)i * C_LEN));

        // ---- in-chunk weighted prefix, computed IN PLACE (v4[i] <- P_i)
        const bool has_t0 = (tile == 0) && (k == 0);
        float P[4]   = {0.0f, 0.0f, 0.0f, 0.0f};
        float apr[4] = {ap[0], ap[1], ap[2], ap[3]};
        #pragma unroll
        for (int i = 0; i < LT; i++) {
            float xv[4] = {v4[i].x, v4[i].y, v4[i].z, v4[i].w};
            #pragma unroll
            for (int j = 0; j < 4; j++) {
                float wm = (has_t0 && i == 0) ? 1.0f : oma[j];
                P[j] = fmaf(xv[j] * wm, apr[j], P[j]);
                apr[j] *= a[j];
            }
            v4[i] = make_float4(P[0], P[1], P[2], P[3]);
        }
        *(float4*)&sm_part[p][k][cg * 4] = v4[LT - 1];   // chunk total
        __syncthreads();

        // ---- base = running total + exclusive prefix over chunks
        float base[4];
        {
            float4 bb = *(const float4*)&sm_base[p][cg * 4];
            base[0] = bb.x; base[1] = bb.y; base[2] = bb.z; base[3] = bb.w;
        }
        for (int j = 0; j < k; j++) {
            float4 pp = *(const float4*)&sm_part[p][j][cg * 4];
            base[0] += pp.x; base[1] += pp.y; base[2] += pp.z; base[3] += pp.w;
        }
        if (k == NCHUNK - 1)
            *(float4*)&sm_base[p ^ 1][cg * 4] = make_float4(
                base[0] + P[0], base[1] + P[1], base[2] + P[2], base[3] + P[3]);

        // ---- y = (base + prefix) * min(a^-t, 1e8), STG.128 out
        float iapr[4] = {iap[0], iap[1], iap[2], iap[3]};
        #pragma unroll
        for (int i = 0; i < LT; i++) {
            float pv[4] = {v4[i].x, v4[i].y, v4[i].z, v4[i].w};
            float yv[4];
            #pragma unroll
            for (int j = 0; j < 4; j++) {
                yv[j] = (base[j] + pv[j]) * fminf(iapr[j], INV_EPS);
                iapr[j] *= inv_a[j];
            }
            __stcs((float4*)(yp + (size_t)i * C_LEN),
                   make_float4(yv[0], yv[1], yv[2], yv[3]));
        }

        // advance chunk-start powers by one tile (128 t)
        #pragma unroll
        for (int j = 0; j < 4; j++) { ap[j] *= aT[j]; iap[j] *= iaT[j]; }
    }
}

extern "C" void kernel_launch(void* const* d_in, const int* in_sizes, int n_in,
                              void* d_out, int out_size)
{
    const float* x  = (const float*)d_in[0];
    const float* la = (const float*)d_in[1];
    float*       y  = (float*)d_out;

    int B = in_sizes[0] / (T_LEN * C_LEN);        // 32
    int blocks = B * (C_LEN / CT);                // 1024
    ema_fused<<<blocks, 128>>>(x, la, y);
}